// round 7
// baseline (speedup 1.0000x reference)
#include <cuda_runtime.h>
#include <cuda_fp16.h>
#include <mma.h>
#include <math.h>

using namespace nvcuda;

// Problem constants (fixed by dataset)
#define NN 20000
#define NPAD 20032                        /* NN rounded up to 64 */
#define EE 100000
#define CC 32
#define NHEAD 4
#define DH 8
#define NB 16
#define HID 64

// ---------------------------------------------------------------------------
// Static scratch (no allocation allowed)
// ---------------------------------------------------------------------------
__device__ float  g_qw[NN * CC];          // per-node (q @ wdot), per head
__device__ float  g_Pbk[NN * CC];         // b2 bias term, K path (scaled)
__device__ float  g_Pbv[NN * CC];         // b2 bias term, V path
// P layout: [n][hb][k][t], index = n*2048 + hb*256 + k*8 + t, h = hb*8+t
__device__ __half g_Pk16[(size_t)NN * 2048];
__device__ __half g_Pv16[(size_t)NN * 2048];
__device__ __half g_W2h[2][32 * 2048];    // fp16 transposed+scaled w2
__device__ __half g_nf16[NPAD * CC];      // fp16 copy of node_features (padded)
__device__ float  g_den[NN * NHEAD];
__device__ float  g_num[NN * CC];
__device__ int    g_cnt[NN];
__device__ int    g_ofs[NN];
__device__ int    g_blk[32];              // per-block sums for scan
__device__ int    g_eorder[EE];

#define INV_SQRT_C 0.17677669529663687f   /* 1/sqrt(32) */
#define DOT_SCALE  0.04419417382415922f   /* (1/8) * (1/sqrt(8)) */
#define SCAN_BLK 20                        /* ceil(20000/1024) */

__device__ __forceinline__ float decode_scalar(const int* p) {
    int iv = *p;
    if (iv > -(1 << 23) && iv < (1 << 23)) return (float)iv;
    return __int_as_float(iv);
}

// ---------------------------------------------------------------------------
// KPRE: fused prologue — zero accumulators, transpose w2 -> fp16 (scaled),
//       convert nf -> fp16. (histogram kept separate: needs g_cnt zeroed)
// ---------------------------------------------------------------------------
__global__ void kpre(const float* __restrict__ nf,
                     const float* __restrict__ w2k,
                     const float* __restrict__ w2v, int n) {
    int i = blockIdx.x * blockDim.x + threadIdx.x;
    int a = n * CC;                 // g_num zero
    int b = a + n * NHEAD;          // g_den zero
    int c = b + n;                  // g_cnt zero
    int d = c + 2 * 65536;          // w2 transpose
    int f = d + n * CC;             // nf16 convert
    if (i < a) {
        g_num[i] = 0.f;
    } else if (i < b) {
        g_den[i - a] = 0.f;
    } else if (i < c) {
        g_cnt[i - b] = 0;
    } else if (i < d) {
        int o = i - c;
        int p = o >> 16;
        int q = o & 65535;
        int ii = q >> 11;           // input channel 0..31
        int j = q & 2047;
        int hb = j >> 8;
        int rem = j & 255;
        int k = rem >> 3;           // output channel 0..31
        int t = rem & 7;
        int h = hb * 8 + t;         // hidden unit 0..63
        const float* W = p ? w2v : w2k;
        g_W2h[p][q] = __float2half_rn(W[h * 1024 + ii * 32 + k] * INV_SQRT_C);
    } else if (i < f) {
        int o = i - d;
        g_nf16[o] = __float2half_rn(nf[o]);
    }
}

// ---------------------------------------------------------------------------
// CSR build: histogram -> block sums -> scan(+inline base) -> scatter
// ---------------------------------------------------------------------------
__global__ void kh_hist(const int* __restrict__ ei, int e) {
    int i = blockIdx.x * blockDim.x + threadIdx.x;
    if (i < e) atomicAdd(&g_cnt[ei[i]], 1);
}

__global__ void ksA_blocksum(int n) {   // SCAN_BLK blocks x 1024, raw sums
    __shared__ int ws[32];
    int t = threadIdx.x;
    int i = blockIdx.x * 1024 + t;
    int v = (i < n) ? g_cnt[i] : 0;
    int s = v;
#pragma unroll
    for (int off = 1; off < 32; off <<= 1) s += __shfl_xor_sync(0xffffffffu, s, off);
    if ((t & 31) == 0) ws[t >> 5] = s;
    __syncthreads();
    if (t < 32) {
        int x = ws[t];
#pragma unroll
        for (int off = 1; off < 32; off <<= 1) x += __shfl_xor_sync(0xffffffffu, x, off);
        if (t == 0) g_blk[blockIdx.x] = x;
    }
}

__global__ void ksC_scan(int n) {       // local scan + inline base-of-block scan
    __shared__ int ws[32];
    __shared__ int s_base;
    int t = threadIdx.x;
    int warp = t >> 5, lane = t & 31;
    if (t < 32) {
        int v = (t < SCAN_BLK) ? g_blk[t] : 0;
        int s = v;
#pragma unroll
        for (int off = 1; off < 32; off <<= 1) {
            int u = __shfl_up_sync(0xffffffffu, s, off);
            if (t >= off) s += u;
        }
        if (t == blockIdx.x) s_base = s - v;   // exclusive base for this block
    }
    __syncthreads();
    int i = blockIdx.x * 1024 + t;
    int v = (i < n) ? g_cnt[i] : 0;
    int s = v;
#pragma unroll
    for (int off = 1; off < 32; off <<= 1) {
        int u = __shfl_up_sync(0xffffffffu, s, off);
        if (lane >= off) s += u;
    }
    if (lane == 31) ws[warp] = s;
    __syncthreads();
    if (t < 32) {
        int x = ws[t];
#pragma unroll
        for (int off = 1; off < 32; off <<= 1) {
            int u = __shfl_up_sync(0xffffffffu, x, off);
            if (t >= off) x += u;
        }
        ws[t] = x;
    }
    __syncthreads();
    int base = s_base + (warp > 0 ? ws[warp - 1] : 0);
    if (i < n) g_ofs[i] = base + s - v;   // exclusive prefix
}

__global__ void kc_scatter(const int* __restrict__ ei, int e) {
    int i = blockIdx.x * blockDim.x + threadIdx.x;
    if (i < e) {
        int pos = atomicAdd(&g_ofs[ei[i]], 1);
        g_eorder[pos] = i;
    }
}

// ---------------------------------------------------------------------------
// K1: per-node qw = (nf@w_q/ C) @ wdot  (per head), plus b2 bias terms
// ---------------------------------------------------------------------------
__global__ void k1_node_pre(const float* __restrict__ nf,
                            const float* __restrict__ w_q,
                            const float* __restrict__ b2k,
                            const float* __restrict__ b2v,
                            const float* __restrict__ wdot, int n) {
    __shared__ float s_wq[1024], s_bk[1024], s_bv[1024], s_wdot[64];
    for (int i = threadIdx.x; i < 1024; i += blockDim.x) {
        s_wq[i] = w_q[i];
        s_bk[i] = b2k[i];
        s_bv[i] = b2v[i];
    }
    if (threadIdx.x < 64) s_wdot[threadIdx.x] = wdot[threadIdx.x];
    __syncthreads();
    int warp = threadIdx.x >> 5;
    int lane = threadIdx.x & 31;
    int node = blockIdx.x * (blockDim.x >> 5) + warp;
    if (node >= n) return;
    float fv = nf[node * 32 + lane];
    float q = 0.f, bk = 0.f, bv = 0.f;
#pragma unroll
    for (int i = 0; i < 32; i++) {
        float a = __shfl_sync(0xffffffffu, fv, i);
        q  = fmaf(a, s_wq[i * 32 + lane], q);
        bk = fmaf(a, s_bk[i * 32 + lane], bk);
        bv = fmaf(a, s_bv[i * 32 + lane], bv);
    }
    q *= INV_SQRT_C;
    // qw_j = sum_i q_{head,i} * wdot[i][j]   (lane = head*8 + j)
    int head = lane >> 3;
    int j = lane & 7;
    float qw = 0.f;
#pragma unroll
    for (int i = 0; i < DH; i++) {
        float qi = __shfl_sync(0xffffffffu, q, head * 8 + i);
        qw = fmaf(qi, s_wdot[i * 8 + j], qw);
    }
    g_qw[node * 32 + lane]  = qw;
    g_Pbk[node * 32 + lane] = bk * INV_SQRT_C;
    g_Pbv[node * 32 + lane] = bv * INV_SQRT_C;
}

// ---------------------------------------------------------------------------
// K2: P GEMM on tensor cores (wmma fp16 in, fp32 accum, fp16 out).
// (n x 32) @ (32 x 2048).  Block: 64 nodes x 128 cols, 8 warps.
// A, B loaded directly from global; C staged in smem for coalesced stores.
// ---------------------------------------------------------------------------
__global__ void __launch_bounds__(256) k2_wmma(int n) {
    __shared__ __align__(32) float Cs[64][136];
    int path = blockIdx.z;
    const __half* A = g_nf16;
    const __half* B = g_W2h[path];
    __half* P = path ? g_Pv16 : g_Pk16;
    int n0 = blockIdx.x * 64;
    int j0 = blockIdx.y * 128;
    int w = threadIdx.x >> 5;
    int wr = w >> 1;          // row tile 0..3 (16 nodes each)
    int wc = w & 1;           // col group 0..1 (64 cols each)

    wmma::fragment<wmma::accumulator, 16, 16, 16, float> c[4];
#pragma unroll
    for (int t = 0; t < 4; t++) wmma::fill_fragment(c[t], 0.f);

#pragma unroll
    for (int kk = 0; kk < 2; kk++) {
        wmma::fragment<wmma::matrix_a, 16, 16, 16, __half, wmma::row_major> a;
        wmma::load_matrix_sync(a, A + (size_t)(n0 + wr * 16) * 32 + kk * 16, 32);
#pragma unroll
        for (int t = 0; t < 4; t++) {
            wmma::fragment<wmma::matrix_b, 16, 16, 16, __half, wmma::row_major> b;
            wmma::load_matrix_sync(b, B + (size_t)(kk * 16) * 2048 + j0 + wc * 64 + t * 16, 2048);
            wmma::mma_sync(c[t], a, b, c[t]);
        }
    }
#pragma unroll
    for (int t = 0; t < 4; t++)
        wmma::store_matrix_sync(&Cs[wr * 16][wc * 64 + t * 16], c[t], 136,
                                wmma::mem_row_major);
    __syncthreads();

    // convert + coalesced fp16 stores: 64 rows x 128 cols, 8 halves/thread
#pragma unroll
    for (int it = 0; it < 4; it++) {
        int idx = it * 256 + threadIdx.x;
        int r = idx >> 4;
        int c8 = (idx & 15) * 8;
        int node = n0 + r;
        if (node < n) {
            __half h[8];
#pragma unroll
            for (int u = 0; u < 8; u++) h[u] = __float2half_rn(Cs[r][c8 + u]);
            *(uint4*)(P + (size_t)node * 2048 + j0 + c8) = *(uint4*)h;
        }
    }
}

// ---------------------------------------------------------------------------
// K3: fused edge pass, src-sorted, coalesced interleaved-fp16 P gather.
// One warp per edge; lane = channel k.
// ---------------------------------------------------------------------------
__global__ void __launch_bounds__(256) k3_edge(
    const int* __restrict__ ei, const float* __restrict__ esh,
    const float* __restrict__ remb, const float* __restrict__ elen,
    const float* __restrict__ w1k, const float* __restrict__ b1k,
    const float* __restrict__ w1v, const float* __restrict__ b1v,
    const int* __restrict__ maxr_p, int e_count) {
    __shared__ float s_w1k[NB * HID], s_w1v[NB * HID];
    __shared__ float s_b1k[HID], s_b1v[HID];
    __shared__ float s_h[8][128];        // per-warp hidden: [K 0..63][V 64..127]
    for (int i = threadIdx.x; i < NB * HID; i += blockDim.x) {
        s_w1k[i] = w1k[i];
        s_w1v[i] = w1v[i];
    }
    if (threadIdx.x < HID) {
        s_b1k[threadIdx.x] = b1k[threadIdx.x];
        s_b1v[threadIdx.x] = b1v[threadIdx.x];
    }
    __syncthreads();

    int warp = threadIdx.x >> 5;
    int lane = threadIdx.x & 31;
    int widx = blockIdx.x * (blockDim.x >> 5) + warp;
    if (widx >= e_count) return;
    int e = g_eorder[widx];

    int src = ei[e];
    int dst = ei[e_count + e];
    float shv = esh[e];

    // radial MLP layer 1 + SiLU (lane owns hidden units lane, lane+32)
    float rv = (lane < NB) ? remb[(size_t)e * NB + lane] : 0.f;
    float zk0 = s_b1k[lane], zk1 = s_b1k[lane + 32];
    float zv0 = s_b1v[lane], zv1 = s_b1v[lane + 32];
#pragma unroll
    for (int r = 0; r < NB; r++) {
        float x = __shfl_sync(0xffffffffu, rv, r);
        zk0 = fmaf(x, s_w1k[r * HID + lane], zk0);
        zk1 = fmaf(x, s_w1k[r * HID + lane + 32], zk1);
        zv0 = fmaf(x, s_w1v[r * HID + lane], zv0);
        zv1 = fmaf(x, s_w1v[r * HID + lane + 32], zv1);
    }
    s_h[warp][lane]      = zk0 / (1.f + __expf(-zk0));
    s_h[warp][lane + 32] = zk1 / (1.f + __expf(-zk1));
    s_h[warp][lane + 64] = zv0 / (1.f + __expf(-zv0));
    s_h[warp][lane + 96] = zv1 / (1.f + __expf(-zv1));
    __syncwarp();

    // contract hidden with fp16 P rows (coalesced: lane stride 16B per load)
    const uint4* pk4 = (const uint4*)(g_Pk16 + (size_t)src * 2048 + lane * 8);
    const uint4* pv4 = (const uint4*)(g_Pv16 + (size_t)src * 2048 + lane * 8);
    float ak = g_Pbk[src * 32 + lane];
    float av = g_Pbv[src * 32 + lane];
#pragma unroll
    for (int hb = 0; hb < 8; hb++) {
        uint4 vk = pk4[hb * 32];
        uint4 vv = pv4[hb * 32];
        const __half2* hk = (const __half2*)&vk;
        const __half2* hv = (const __half2*)&vv;
#pragma unroll
        for (int u = 0; u < 4; u++) {
            float2 hidk = *(const float2*)&s_h[warp][hb * 8 + 2 * u];
            float2 hidv = *(const float2*)&s_h[warp][64 + hb * 8 + 2 * u];
            float2 pk = __half22float2(hk[u]);
            float2 pv = __half22float2(hv[u]);
            ak = fmaf(hidk.x, pk.x, ak);
            ak = fmaf(hidk.y, pk.y, ak);
            av = fmaf(hidv.x, pv.x, av);
            av = fmaf(hidv.y, pv.y, av);
        }
    }
    float k_e = shv * ak;
    float v_e = shv * av;

    // logit = sum_j qw_j * k_j per head (qw precomputed in k1)
    float prod = g_qw[dst * 32 + lane] * k_e;
    prod += __shfl_xor_sync(0xffffffffu, prod, 1);
    prod += __shfl_xor_sync(0xffffffffu, prod, 2);
    prod += __shfl_xor_sync(0xffffffffu, prod, 4);

    float max_r = decode_scalar(maxr_p);
    float L = elen[e];
    float cut = 1.f / (1.f + __expf(-10.f * (1.f - L / max_r)));
    float logit = prod * DOT_SCALE * cut;
    float ex = __expf(logit);    // |logit| << 1 by construction; no max-shift

    int head = lane >> 3;
    if ((lane & 7) == 0) atomicAdd(&g_den[dst * NHEAD + head], ex);
    atomicAdd(&g_num[dst * 32 + lane], ex * v_e);
}

// ---------------------------------------------------------------------------
// K5: per-node epilogue
// ---------------------------------------------------------------------------
__global__ void k5_final(const float* __restrict__ nf,
                         const float* __restrict__ w_out,
                         const float* __restrict__ ffn_w1,
                         const float* __restrict__ ffn_w2,
                         float* __restrict__ out, int n) {
    __shared__ float s_wo[1024], s_f1[2048], s_f2[2048];
    for (int i = threadIdx.x; i < 1024; i += blockDim.x) s_wo[i] = w_out[i];
    for (int i = threadIdx.x; i < 2048; i += blockDim.x) {
        s_f1[i] = ffn_w1[i];
        s_f2[i] = ffn_w2[i];
    }
    __syncthreads();
    int warp = threadIdx.x >> 5;
    int lane = threadIdx.x & 31;
    int node = blockIdx.x * (blockDim.x >> 5) + warp;
    if (node >= n) return;

    float numv = g_num[node * 32 + lane];
    float den = g_den[node * NHEAD + (lane >> 3)];
    float agg = (den > 0.f) ? numv / den : 0.f;

    float o = 0.f;
#pragma unroll
    for (int i = 0; i < 32; i++) {
        float a = __shfl_sync(0xffffffffu, agg, i);
        o = fmaf(a, s_wo[i * 32 + lane], o);
    }
    float attn = nf[node * 32 + lane] + o * INV_SQRT_C;

    float h0 = 0.f, h1 = 0.f;
#pragma unroll
    for (int i = 0; i < 32; i++) {
        float a = __shfl_sync(0xffffffffu, attn, i);
        h0 = fmaf(a, s_f1[i * 64 + lane], h0);
        h1 = fmaf(a, s_f1[i * 64 + lane + 32], h1);
    }
    h0 *= INV_SQRT_C;
    h1 *= INV_SQRT_C;
    float g0 = h0 / (1.f + expf(-fabsf(h0)));
    float g1 = h1 / (1.f + expf(-fabsf(h1)));

    float f = 0.f;
#pragma unroll
    for (int jj = 0; jj < 64; jj++) {
        float g = __shfl_sync(0xffffffffu, (jj < 32) ? g0 : g1, jj & 31);
        f = fmaf(g, s_f2[jj * 32 + lane], f);
    }
    out[node * 32 + lane] = attn + f * 0.125f;
}

// ---------------------------------------------------------------------------
extern "C" void kernel_launch(void* const* d_in, const int* in_sizes, int n_in,
                              void* d_out, int out_size) {
    const float* nf     = (const float*)d_in[0];
    const int*   ei     = (const int*)d_in[1];
    const float* esh    = (const float*)d_in[2];
    const float* remb   = (const float*)d_in[3];
    const float* elen   = (const float*)d_in[4];
    const int*   maxr   = (const int*)d_in[5];
    const float* w_q    = (const float*)d_in[6];
    const float* fck_w1 = (const float*)d_in[7];
    const float* fck_b1 = (const float*)d_in[8];
    const float* fck_w2 = (const float*)d_in[9];
    const float* fck_b2 = (const float*)d_in[10];
    const float* fcv_w1 = (const float*)d_in[11];
    const float* fcv_b1 = (const float*)d_in[12];
    const float* fcv_w2 = (const float*)d_in[13];
    const float* fcv_b2 = (const float*)d_in[14];
    const float* w_dot  = (const float*)d_in[15];
    const float* w_out  = (const float*)d_in[16];
    const float* ffn_w1 = (const float*)d_in[17];
    const float* ffn_w2 = (const float*)d_in[18];

    int n = in_sizes[0] / CC;
    int e = in_sizes[1] / 2;

    int totpre = n * (CC + NHEAD + 1) + 2 * 65536 + n * CC;
    kpre<<<(totpre + 255) / 256, 256>>>(nf, fck_w2, fcv_w2, n);
    kh_hist<<<(e + 255) / 256, 256>>>(ei, e);
    ksA_blocksum<<<SCAN_BLK, 1024>>>(n);
    ksC_scan<<<SCAN_BLK, 1024>>>(n);
    kc_scatter<<<(e + 255) / 256, 256>>>(ei, e);
    k1_node_pre<<<(n + 7) / 8, 256>>>(nf, w_q, fck_b2, fcv_b2, w_dot, n);
    dim3 g2((n + 63) / 64, 16, 2);
    k2_wmma<<<g2, 256>>>(n);
    k3_edge<<<(e + 7) / 8, 256>>>(ei, esh, remb, elen, fck_w1, fck_b1,
                                  fcv_w1, fcv_b1, maxr, e);
    k5_final<<<(n + 7) / 8, 256>>>(nf, w_out, ffn_w1, ffn_w2, (float*)d_out, n);
}

// round 8
// speedup vs baseline: 1.3066x; 1.3066x over previous
#include <cuda_runtime.h>
#include <cuda_fp16.h>
#include <mma.h>
#include <math.h>

using namespace nvcuda;

// Problem constants (fixed by dataset)
#define NN 20000
#define NPAD 20032                        /* NN rounded up to 64 */
#define EE 100000
#define CC 32
#define NHEAD 4
#define DH 8
#define NB 16
#define HID 64

// ---------------------------------------------------------------------------
// Static scratch (no allocation allowed)
// ---------------------------------------------------------------------------
__device__ float  g_qw[NN * CC];          // per-node (q @ wdot), per head
__device__ float  g_Pbk[NN * CC];         // b2 bias term, K path (scaled)
__device__ float  g_Pbv[NN * CC];         // b2 bias term, V path
// P layout: [n][hb][k][t], index = n*2048 + hb*256 + k*8 + t, h = hb*8+t
__device__ __half g_Pk16[(size_t)NN * 2048];
__device__ __half g_Pv16[(size_t)NN * 2048];
__device__ __half g_W2h[2][32 * 2048];    // fp16 transposed+scaled w2
__device__ __half g_nf16[NPAD * CC];      // fp16 copy of node_features (padded)
__device__ float  g_den[NN * NHEAD];
__device__ float  g_num[NN * CC];
__device__ int    g_cnt[NN];
__device__ int    g_ofs[NN];
__device__ int    g_blk[32];              // per-block sums for scan
__device__ int    g_eorder[EE];

#define INV_SQRT_C 0.17677669529663687f   /* 1/sqrt(32) */
#define DOT_SCALE  0.04419417382415922f   /* (1/8) * (1/sqrt(8)) */
#define SCAN_BLK 20                        /* ceil(20000/1024) */

__device__ __forceinline__ float decode_scalar(const int* p) {
    int iv = *p;
    if (iv > -(1 << 23) && iv < (1 << 23)) return (float)iv;
    return __int_as_float(iv);
}

// ---------------------------------------------------------------------------
// KPRE: fused prologue — zero accumulators, transpose w2 -> fp16 (scaled),
//       convert nf -> fp16.
// ---------------------------------------------------------------------------
__global__ void kpre(const float* __restrict__ nf,
                     const float* __restrict__ w2k,
                     const float* __restrict__ w2v, int n) {
    int i = blockIdx.x * blockDim.x + threadIdx.x;
    int a = n * CC;                 // g_num zero
    int b = a + n * NHEAD;          // g_den zero
    int c = b + n;                  // g_cnt zero
    int d = c + 2 * 65536;          // w2 transpose
    int f = d + n * CC;             // nf16 convert
    if (i < a) {
        g_num[i] = 0.f;
    } else if (i < b) {
        g_den[i - a] = 0.f;
    } else if (i < c) {
        g_cnt[i - b] = 0;
    } else if (i < d) {
        int o = i - c;
        int p = o >> 16;
        int q = o & 65535;
        int ii = q >> 11;           // input channel 0..31
        int j = q & 2047;
        int hb = j >> 8;
        int rem = j & 255;
        int k = rem >> 3;           // output channel 0..31
        int t = rem & 7;
        int h = hb * 8 + t;         // hidden unit 0..63
        const float* W = p ? w2v : w2k;
        g_W2h[p][q] = __float2half_rn(W[h * 1024 + ii * 32 + k] * INV_SQRT_C);
    } else if (i < f) {
        int o = i - d;
        g_nf16[o] = __float2half_rn(nf[o]);
    }
}

// ---------------------------------------------------------------------------
// CSR build: histogram -> block sums -> scan(+inline base) -> scatter
// ---------------------------------------------------------------------------
__global__ void kh_hist(const int* __restrict__ ei, int e) {
    int i = blockIdx.x * blockDim.x + threadIdx.x;
    if (i < e) atomicAdd(&g_cnt[ei[i]], 1);
}

__global__ void ksA_blocksum(int n) {   // SCAN_BLK blocks x 1024, raw sums
    __shared__ int ws[32];
    int t = threadIdx.x;
    int i = blockIdx.x * 1024 + t;
    int v = (i < n) ? g_cnt[i] : 0;
    int s = v;
#pragma unroll
    for (int off = 1; off < 32; off <<= 1) s += __shfl_xor_sync(0xffffffffu, s, off);
    if ((t & 31) == 0) ws[t >> 5] = s;
    __syncthreads();
    if (t < 32) {
        int x = ws[t];
#pragma unroll
        for (int off = 1; off < 32; off <<= 1) x += __shfl_xor_sync(0xffffffffu, x, off);
        if (t == 0) g_blk[blockIdx.x] = x;
    }
}

__global__ void ksC_scan(int n) {       // local scan + inline base-of-block scan
    __shared__ int ws[32];
    __shared__ int s_base;
    int t = threadIdx.x;
    int warp = t >> 5, lane = t & 31;
    if (t < 32) {
        int v = (t < SCAN_BLK) ? g_blk[t] : 0;
        int s = v;
#pragma unroll
        for (int off = 1; off < 32; off <<= 1) {
            int u = __shfl_up_sync(0xffffffffu, s, off);
            if (t >= off) s += u;
        }
        if (t == blockIdx.x) s_base = s - v;   // exclusive base for this block
    }
    __syncthreads();
    int i = blockIdx.x * 1024 + t;
    int v = (i < n) ? g_cnt[i] : 0;
    int s = v;
#pragma unroll
    for (int off = 1; off < 32; off <<= 1) {
        int u = __shfl_up_sync(0xffffffffu, s, off);
        if (lane >= off) s += u;
    }
    if (lane == 31) ws[warp] = s;
    __syncthreads();
    if (t < 32) {
        int x = ws[t];
#pragma unroll
        for (int off = 1; off < 32; off <<= 1) {
            int u = __shfl_up_sync(0xffffffffu, x, off);
            if (t >= off) x += u;
        }
        ws[t] = x;
    }
    __syncthreads();
    int base = s_base + (warp > 0 ? ws[warp - 1] : 0);
    if (i < n) g_ofs[i] = base + s - v;   // exclusive prefix
}

__global__ void kc_scatter(const int* __restrict__ ei, int e) {
    int i = blockIdx.x * blockDim.x + threadIdx.x;
    if (i < e) {
        int pos = atomicAdd(&g_ofs[ei[i]], 1);
        g_eorder[pos] = i;
    }
}

// ---------------------------------------------------------------------------
// K1: per-node qw = ((nf@w_q)/sqrt(C)) @ wdot  (per head), plus b2 bias terms
// ---------------------------------------------------------------------------
__global__ void k1_node_pre(const float* __restrict__ nf,
                            const float* __restrict__ w_q,
                            const float* __restrict__ b2k,
                            const float* __restrict__ b2v,
                            const float* __restrict__ wdot, int n) {
    __shared__ float s_wq[1024], s_bk[1024], s_bv[1024], s_wdot[64];
    for (int i = threadIdx.x; i < 1024; i += blockDim.x) {
        s_wq[i] = w_q[i];
        s_bk[i] = b2k[i];
        s_bv[i] = b2v[i];
    }
    if (threadIdx.x < 64) s_wdot[threadIdx.x] = wdot[threadIdx.x];
    __syncthreads();
    int warp = threadIdx.x >> 5;
    int lane = threadIdx.x & 31;
    int node = blockIdx.x * (blockDim.x >> 5) + warp;
    if (node >= n) return;
    float fv = nf[node * 32 + lane];
    float q = 0.f, bk = 0.f, bv = 0.f;
#pragma unroll
    for (int i = 0; i < 32; i++) {
        float a = __shfl_sync(0xffffffffu, fv, i);
        q  = fmaf(a, s_wq[i * 32 + lane], q);
        bk = fmaf(a, s_bk[i * 32 + lane], bk);
        bv = fmaf(a, s_bv[i * 32 + lane], bv);
    }
    q *= INV_SQRT_C;
    int head = lane >> 3;
    int j = lane & 7;
    float qw = 0.f;
#pragma unroll
    for (int i = 0; i < DH; i++) {
        float qi = __shfl_sync(0xffffffffu, q, head * 8 + i);
        qw = fmaf(qi, s_wdot[i * 8 + j], qw);
    }
    g_qw[node * 32 + lane]  = qw;
    g_Pbk[node * 32 + lane] = bk * INV_SQRT_C;
    g_Pbv[node * 32 + lane] = bv * INV_SQRT_C;
}

// ---------------------------------------------------------------------------
// K2: P GEMM on tensor cores, SMEM-STAGED (LDSM path, not global frag loads).
// (n x 32) @ (32 x 2048).  Block: 64 nodes x 128 cols, 8 warps.
//   As[64][40]  (row stride 80B  -> ldmatrix conflict-free: 20r mod 32 distinct)
//   Bs[32][136] (row stride 272B -> 4r mod 32 distinct)
// ---------------------------------------------------------------------------
__global__ void __launch_bounds__(256) k2_wmma(int n) {
    __shared__ __align__(16) __half As[64][40];
    __shared__ __align__(16) __half Bs[32][136];
    __shared__ __align__(32) float Cs[64][136];
    int path = blockIdx.z;
    const __half* B = g_W2h[path];
    __half* P = path ? g_Pv16 : g_Pk16;
    int n0 = blockIdx.x * 64;
    int j0 = blockIdx.y * 128;
    int tid = threadIdx.x;

    // Stage A: 64 x 32 halves = 256 uint4, one per thread
    {
        int node = tid >> 2;
        int q8 = (tid & 3) * 8;
        uint4 v = *(const uint4*)(g_nf16 + (size_t)(n0 + node) * 32 + q8);
        *(uint4*)(&As[node][q8]) = v;
    }
    // Stage B: 32 x 128 halves = 512 uint4, two per thread
#pragma unroll
    for (int p = 0; p < 2; p++) {
        int idx = p * 256 + tid;
        int r = idx >> 4;
        int c8 = (idx & 15) * 8;
        uint4 v = *(const uint4*)(B + (size_t)r * 2048 + j0 + c8);
        *(uint4*)(&Bs[r][c8]) = v;
    }
    __syncthreads();

    int w = tid >> 5;
    int wr = w >> 1;          // row tile 0..3 (16 nodes each)
    int wc = w & 1;           // col group 0..1 (64 cols each)

    wmma::fragment<wmma::accumulator, 16, 16, 16, float> c[4];
#pragma unroll
    for (int t = 0; t < 4; t++) wmma::fill_fragment(c[t], 0.f);

#pragma unroll
    for (int kk = 0; kk < 2; kk++) {
        wmma::fragment<wmma::matrix_a, 16, 16, 16, __half, wmma::row_major> a;
        wmma::load_matrix_sync(a, &As[wr * 16][kk * 16], 40);
#pragma unroll
        for (int t = 0; t < 4; t++) {
            wmma::fragment<wmma::matrix_b, 16, 16, 16, __half, wmma::row_major> b;
            wmma::load_matrix_sync(b, &Bs[kk * 16][wc * 64 + t * 16], 136);
            wmma::mma_sync(c[t], a, b, c[t]);
        }
    }
#pragma unroll
    for (int t = 0; t < 4; t++)
        wmma::store_matrix_sync(&Cs[wr * 16][wc * 64 + t * 16], c[t], 136,
                                wmma::mem_row_major);
    __syncthreads();

    // convert + coalesced fp16 stores: 64 rows x 128 cols, 8 halves/thread
#pragma unroll
    for (int it = 0; it < 4; it++) {
        int idx = it * 256 + tid;
        int r = idx >> 4;
        int c8 = (idx & 15) * 8;
        int node = n0 + r;
        if (node < n) {
            __half h[8];
#pragma unroll
            for (int u = 0; u < 8; u++) h[u] = __float2half_rn(Cs[r][c8 + u]);
            *(uint4*)(P + (size_t)node * 2048 + j0 + c8) = *(uint4*)h;
        }
    }
}

// ---------------------------------------------------------------------------
// K3: fused edge pass, src-sorted, coalesced interleaved-fp16 P gather.
// One warp per edge; lane = channel k.
// ---------------------------------------------------------------------------
__global__ void __launch_bounds__(256) k3_edge(
    const int* __restrict__ ei, const float* __restrict__ esh,
    const float* __restrict__ remb, const float* __restrict__ elen,
    const float* __restrict__ w1k, const float* __restrict__ b1k,
    const float* __restrict__ w1v, const float* __restrict__ b1v,
    const int* __restrict__ maxr_p, int e_count) {
    __shared__ float s_w1k[NB * HID], s_w1v[NB * HID];
    __shared__ float s_b1k[HID], s_b1v[HID];
    __shared__ float s_h[8][128];        // per-warp hidden: [K 0..63][V 64..127]
    for (int i = threadIdx.x; i < NB * HID; i += blockDim.x) {
        s_w1k[i] = w1k[i];
        s_w1v[i] = w1v[i];
    }
    if (threadIdx.x < HID) {
        s_b1k[threadIdx.x] = b1k[threadIdx.x];
        s_b1v[threadIdx.x] = b1v[threadIdx.x];
    }
    __syncthreads();

    int warp = threadIdx.x >> 5;
    int lane = threadIdx.x & 31;
    int widx = blockIdx.x * (blockDim.x >> 5) + warp;
    if (widx >= e_count) return;
    int e = g_eorder[widx];

    int src = ei[e];
    int dst = ei[e_count + e];
    float shv = esh[e];

    // radial MLP layer 1 + SiLU (lane owns hidden units lane, lane+32)
    float rv = (lane < NB) ? remb[(size_t)e * NB + lane] : 0.f;
    float zk0 = s_b1k[lane], zk1 = s_b1k[lane + 32];
    float zv0 = s_b1v[lane], zv1 = s_b1v[lane + 32];
#pragma unroll
    for (int r = 0; r < NB; r++) {
        float x = __shfl_sync(0xffffffffu, rv, r);
        zk0 = fmaf(x, s_w1k[r * HID + lane], zk0);
        zk1 = fmaf(x, s_w1k[r * HID + lane + 32], zk1);
        zv0 = fmaf(x, s_w1v[r * HID + lane], zv0);
        zv1 = fmaf(x, s_w1v[r * HID + lane + 32], zv1);
    }
    s_h[warp][lane]      = zk0 / (1.f + __expf(-zk0));
    s_h[warp][lane + 32] = zk1 / (1.f + __expf(-zk1));
    s_h[warp][lane + 64] = zv0 / (1.f + __expf(-zv0));
    s_h[warp][lane + 96] = zv1 / (1.f + __expf(-zv1));
    __syncwarp();

    // contract hidden with fp16 P rows (coalesced: lane stride 16B per load)
    const uint4* pk4 = (const uint4*)(g_Pk16 + (size_t)src * 2048 + lane * 8);
    const uint4* pv4 = (const uint4*)(g_Pv16 + (size_t)src * 2048 + lane * 8);
    float ak = g_Pbk[src * 32 + lane];
    float av = g_Pbv[src * 32 + lane];
#pragma unroll
    for (int hb = 0; hb < 8; hb++) {
        uint4 vk = pk4[hb * 32];
        uint4 vv = pv4[hb * 32];
        const __half2* hk = (const __half2*)&vk;
        const __half2* hv = (const __half2*)&vv;
#pragma unroll
        for (int u = 0; u < 4; u++) {
            float2 hidk = *(const float2*)&s_h[warp][hb * 8 + 2 * u];
            float2 hidv = *(const float2*)&s_h[warp][64 + hb * 8 + 2 * u];
            float2 pk = __half22float2(hk[u]);
            float2 pv = __half22float2(hv[u]);
            ak = fmaf(hidk.x, pk.x, ak);
            ak = fmaf(hidk.y, pk.y, ak);
            av = fmaf(hidv.x, pv.x, av);
            av = fmaf(hidv.y, pv.y, av);
        }
    }
    float k_e = shv * ak;
    float v_e = shv * av;

    // logit = sum_j qw_j * k_j per head (qw precomputed in k1)
    float prod = g_qw[dst * 32 + lane] * k_e;
    prod += __shfl_xor_sync(0xffffffffu, prod, 1);
    prod += __shfl_xor_sync(0xffffffffu, prod, 2);
    prod += __shfl_xor_sync(0xffffffffu, prod, 4);

    float max_r = decode_scalar(maxr_p);
    float L = elen[e];
    float cut = 1.f / (1.f + __expf(-10.f * (1.f - L / max_r)));
    float logit = prod * DOT_SCALE * cut;
    float ex = __expf(logit);    // |logit| << 1 by construction; no max-shift

    int head = lane >> 3;
    if ((lane & 7) == 0) atomicAdd(&g_den[dst * NHEAD + head], ex);
    atomicAdd(&g_num[dst * 32 + lane], ex * v_e);
}

// ---------------------------------------------------------------------------
// K5: per-node epilogue
// ---------------------------------------------------------------------------
__global__ void k5_final(const float* __restrict__ nf,
                         const float* __restrict__ w_out,
                         const float* __restrict__ ffn_w1,
                         const float* __restrict__ ffn_w2,
                         float* __restrict__ out, int n) {
    __shared__ float s_wo[1024], s_f1[2048], s_f2[2048];
    for (int i = threadIdx.x; i < 1024; i += blockDim.x) s_wo[i] = w_out[i];
    for (int i = threadIdx.x; i < 2048; i += blockDim.x) {
        s_f1[i] = ffn_w1[i];
        s_f2[i] = ffn_w2[i];
    }
    __syncthreads();
    int warp = threadIdx.x >> 5;
    int lane = threadIdx.x & 31;
    int node = blockIdx.x * (blockDim.x >> 5) + warp;
    if (node >= n) return;

    float numv = g_num[node * 32 + lane];
    float den = g_den[node * NHEAD + (lane >> 3)];
    float agg = (den > 0.f) ? numv / den : 0.f;

    float o = 0.f;
#pragma unroll
    for (int i = 0; i < 32; i++) {
        float a = __shfl_sync(0xffffffffu, agg, i);
        o = fmaf(a, s_wo[i * 32 + lane], o);
    }
    float attn = nf[node * 32 + lane] + o * INV_SQRT_C;

    float h0 = 0.f, h1 = 0.f;
#pragma unroll
    for (int i = 0; i < 32; i++) {
        float a = __shfl_sync(0xffffffffu, attn, i);
        h0 = fmaf(a, s_f1[i * 64 + lane], h0);
        h1 = fmaf(a, s_f1[i * 64 + lane + 32], h1);
    }
    h0 *= INV_SQRT_C;
    h1 *= INV_SQRT_C;
    float g0 = h0 / (1.f + expf(-fabsf(h0)));
    float g1 = h1 / (1.f + expf(-fabsf(h1)));

    float f = 0.f;
#pragma unroll
    for (int jj = 0; jj < 64; jj++) {
        float g = __shfl_sync(0xffffffffu, (jj < 32) ? g0 : g1, jj & 31);
        f = fmaf(g, s_f2[jj * 32 + lane], f);
    }
    out[node * 32 + lane] = attn + f * 0.125f;
}

// ---------------------------------------------------------------------------
extern "C" void kernel_launch(void* const* d_in, const int* in_sizes, int n_in,
                              void* d_out, int out_size) {
    const float* nf     = (const float*)d_in[0];
    const int*   ei     = (const int*)d_in[1];
    const float* esh    = (const float*)d_in[2];
    const float* remb   = (const float*)d_in[3];
    const float* elen   = (const float*)d_in[4];
    const int*   maxr   = (const int*)d_in[5];
    const float* w_q    = (const float*)d_in[6];
    const float* fck_w1 = (const float*)d_in[7];
    const float* fck_b1 = (const float*)d_in[8];
    const float* fck_w2 = (const float*)d_in[9];
    const float* fck_b2 = (const float*)d_in[10];
    const float* fcv_w1 = (const float*)d_in[11];
    const float* fcv_b1 = (const float*)d_in[12];
    const float* fcv_w2 = (const float*)d_in[13];
    const float* fcv_b2 = (const float*)d_in[14];
    const float* w_dot  = (const float*)d_in[15];
    const float* w_out  = (const float*)d_in[16];
    const float* ffn_w1 = (const float*)d_in[17];
    const float* ffn_w2 = (const float*)d_in[18];

    int n = in_sizes[0] / CC;
    int e = in_sizes[1] / 2;

    int totpre = n * (CC + NHEAD + 1) + 2 * 65536 + n * CC;
    kpre<<<(totpre + 255) / 256, 256>>>(nf, fck_w2, fcv_w2, n);
    kh_hist<<<(e + 255) / 256, 256>>>(ei, e);
    ksA_blocksum<<<SCAN_BLK, 1024>>>(n);
    ksC_scan<<<SCAN_BLK, 1024>>>(n);
    kc_scatter<<<(e + 255) / 256, 256>>>(ei, e);
    k1_node_pre<<<(n + 7) / 8, 256>>>(nf, w_q, fck_b2, fcv_b2, w_dot, n);
    dim3 g2((n + 63) / 64, 16, 2);
    k2_wmma<<<g2, 256>>>(n);
    k3_edge<<<(e + 7) / 8, 256>>>(ei, esh, remb, elen, fck_w1, fck_b1,
                                  fcv_w1, fcv_b1, maxr, e);
    k5_final<<<(n + 7) / 8, 256>>>(nf, w_out, ffn_w1, ffn_w2, (float*)d_out, n);
}